// round 1
// baseline (speedup 1.0000x reference)
#include <cuda_runtime.h>
#include <cuda_bf16.h>

#define BATCH 64
#define T 512
#define C 384
#define H 64
#define BT (BATCH*T)

// Scratch for projected Q, K, V  (8 MB each) — __device__ globals, no runtime alloc.
__device__ float g_Q[BT * H];
__device__ float g_K[BT * H];
__device__ float g_V[BT * H];

// ---------------------------------------------------------------------------
// Kernel 1: fused QKV projection.
// x: [BT, 384] @ W{q,k,v}: [384, 64] -> g_{Q,K,V}: [BT, 64]
// Block: 256 threads = 16x16, each thread computes a 4x4 tile for all 3 outputs.
// Grid: BT/64 = 512 blocks (64 rows each, full 64-col N).
// ---------------------------------------------------------------------------
__global__ __launch_bounds__(256) void qkv_proj_kernel(
    const float* __restrict__ x,
    const float* __restrict__ Wq,
    const float* __restrict__ Wk,
    const float* __restrict__ Wv)
{
    __shared__ float As[16][68];        // x tile, transposed: As[k][m]
    __shared__ float Bs[3][16][64];     // weight tiles: Bs[w][k][n]

    const int tid = threadIdx.x;
    const int tx = tid & 15;            // n-group
    const int ty = tid >> 4;            // m-group
    const int row0 = blockIdx.x * 64;

    const float* Ws[3] = {Wq, Wk, Wv};

    float acc[3][4][4];
    #pragma unroll
    for (int w = 0; w < 3; ++w)
        #pragma unroll
        for (int i = 0; i < 4; ++i)
            #pragma unroll
            for (int j = 0; j < 4; ++j)
                acc[w][i][j] = 0.0f;

    for (int kt = 0; kt < C / 16; ++kt) {
        // Load 64x16 x-tile (transposed into As[k][m])
        #pragma unroll
        for (int e = 0; e < 4; ++e) {
            int idx = tid + e * 256;
            int r = idx >> 4;           // row within tile (0..63)
            int c = idx & 15;           // k within tile (0..15)
            As[c][r] = x[(row0 + r) * C + kt * 16 + c];
        }
        // Load 16x64 weight tiles for all 3 matrices
        #pragma unroll
        for (int w = 0; w < 3; ++w) {
            #pragma unroll
            for (int e = 0; e < 4; ++e) {
                int idx = tid + e * 256;
                int r = idx >> 6;       // k within tile (0..15)
                int c = idx & 63;       // n (0..63)
                Bs[w][r][c] = Ws[w][(kt * 16 + r) * H + c];
            }
        }
        __syncthreads();

        #pragma unroll
        for (int k = 0; k < 16; ++k) {
            float4 a4 = *(const float4*)&As[k][ty * 4];
            float av[4] = {a4.x, a4.y, a4.z, a4.w};
            #pragma unroll
            for (int w = 0; w < 3; ++w) {
                float4 b4 = *(const float4*)&Bs[w][k][tx * 4];
                float bv[4] = {b4.x, b4.y, b4.z, b4.w};
                #pragma unroll
                for (int i = 0; i < 4; ++i)
                    #pragma unroll
                    for (int j = 0; j < 4; ++j)
                        acc[w][i][j] += av[i] * bv[j];
            }
        }
        __syncthreads();
    }

    float* Outs[3] = {g_Q, g_K, g_V};
    #pragma unroll
    for (int w = 0; w < 3; ++w)
        #pragma unroll
        for (int i = 0; i < 4; ++i) {
            int r = row0 + ty * 4 + i;
            float4 v = make_float4(acc[w][i][0], acc[w][i][1],
                                   acc[w][i][2], acc[w][i][3]);
            *(float4*)&Outs[w][r * H + tx * 4] = v;
        }
}

// ---------------------------------------------------------------------------
// Kernel 2: causal flash attention over projected Q,K,V (fp32, online softmax).
// Grid: (T/64, BATCH). Block: 256 threads = 16(ti) x 16(tj).
// Thread owns 4 query rows (ti*4+ic) x 4 cols; cols are key-slots in QK^T,
// head-dims in PV. Row stats (m,l) replicated across the 16 tj lanes via shfl.
// ---------------------------------------------------------------------------
#define QS_STRIDE 65
#define VS_STRIDE 68
#define ATTN_SMEM_FLOATS (3 * 64 * QS_STRIDE + 64 * VS_STRIDE)
#define ATTN_SMEM_BYTES  (ATTN_SMEM_FLOATS * 4)

__global__ __launch_bounds__(256) void attn_kernel(float* __restrict__ out)
{
    extern __shared__ float sm[];
    float* Qs = sm;                          // [64][65]
    float* Ks = sm + 64 * QS_STRIDE;         // [64][65]
    float* Ps = sm + 2 * 64 * QS_STRIDE;     // [64][65]
    float* Vs = sm + 3 * 64 * QS_STRIDE;     // [64][68] (float4-aligned rows)

    const int tid = threadIdx.x;
    const int tj = tid & 15;
    const int ti = tid >> 4;
    const int qt = blockIdx.x;     // query tile 0..7
    const int b  = blockIdx.y;     // batch
    const float scale = 0.125f;    // 1/sqrt(64)

    // Load Q tile [64][64]
    const int qoff = (b * T + qt * 64) * H;
    #pragma unroll
    for (int e = 0; e < 16; ++e) {
        int idx = tid + e * 256;
        Qs[(idx >> 6) * QS_STRIDE + (idx & 63)] = g_Q[qoff + idx];
    }

    float m[4], l[4], o[4][4];
    #pragma unroll
    for (int ic = 0; ic < 4; ++ic) {
        m[ic] = -1e30f; l[ic] = 0.0f;
        #pragma unroll
        for (int hc = 0; hc < 4; ++hc) o[ic][hc] = 0.0f;
    }

    for (int t = 0; t <= qt; ++t) {
        const int koff = (b * T + t * 64) * H;
        __syncthreads();   // prior-iter Ps/Vs reads done before overwrite
        #pragma unroll
        for (int e = 0; e < 16; ++e) {
            int idx = tid + e * 256;
            int r = idx >> 6, c = idx & 63;
            Ks[r * QS_STRIDE + c] = g_K[koff + idx];
            Vs[r * VS_STRIDE + c] = g_V[koff + idx];
        }
        __syncthreads();

        // --- scores: s[ic][jc] = Q[ti4+ic] . K[tj4+jc] ---
        float s[4][4];
        #pragma unroll
        for (int ic = 0; ic < 4; ++ic)
            #pragma unroll
            for (int jc = 0; jc < 4; ++jc)
                s[ic][jc] = 0.0f;

        #pragma unroll 8
        for (int k = 0; k < 64; ++k) {
            float qv[4], kv[4];
            #pragma unroll
            for (int ic = 0; ic < 4; ++ic) qv[ic] = Qs[(ti * 4 + ic) * QS_STRIDE + k];
            #pragma unroll
            for (int jc = 0; jc < 4; ++jc) kv[jc] = Ks[(tj * 4 + jc) * QS_STRIDE + k];
            #pragma unroll
            for (int ic = 0; ic < 4; ++ic)
                #pragma unroll
                for (int jc = 0; jc < 4; ++jc)
                    s[ic][jc] += qv[ic] * kv[jc];
        }

        const bool last = (t == qt);
        float alpha[4];
        #pragma unroll
        for (int ic = 0; ic < 4; ++ic) {
            float tm = -1e30f;
            #pragma unroll
            for (int jc = 0; jc < 4; ++jc) {
                s[ic][jc] *= scale;
                if (last && (tj * 4 + jc > ti * 4 + ic)) s[ic][jc] = -1e30f;
                tm = fmaxf(tm, s[ic][jc]);
            }
            tm = fmaxf(tm, __shfl_xor_sync(0xffffffffu, tm, 1));
            tm = fmaxf(tm, __shfl_xor_sync(0xffffffffu, tm, 2));
            tm = fmaxf(tm, __shfl_xor_sync(0xffffffffu, tm, 4));
            tm = fmaxf(tm, __shfl_xor_sync(0xffffffffu, tm, 8));
            float mnew = fmaxf(m[ic], tm);
            alpha[ic] = __expf(m[ic] - mnew);
            m[ic] = mnew;
        }

        #pragma unroll
        for (int ic = 0; ic < 4; ++ic) {
            float ls = 0.0f;
            #pragma unroll
            for (int jc = 0; jc < 4; ++jc) {
                float p = __expf(s[ic][jc] - m[ic]);   // masked -> exp(-huge) = 0
                Ps[(ti * 4 + ic) * QS_STRIDE + tj * 4 + jc] = p;
                ls += p;
            }
            ls += __shfl_xor_sync(0xffffffffu, ls, 1);
            ls += __shfl_xor_sync(0xffffffffu, ls, 2);
            ls += __shfl_xor_sync(0xffffffffu, ls, 4);
            ls += __shfl_xor_sync(0xffffffffu, ls, 8);
            l[ic] = l[ic] * alpha[ic] + ls;
            #pragma unroll
            for (int hc = 0; hc < 4; ++hc) o[ic][hc] *= alpha[ic];
        }
        __syncthreads();   // Ps visible to all lanes of each row

        // --- PV: o[ic][hc] += sum_j P[row][j] * V[j][tj4+hc] ---
        #pragma unroll 8
        for (int j = 0; j < 64; ++j) {
            float4 v4 = *(const float4*)&Vs[j * VS_STRIDE + tj * 4];
            float vv[4] = {v4.x, v4.y, v4.z, v4.w};
            #pragma unroll
            for (int ic = 0; ic < 4; ++ic) {
                float p = Ps[(ti * 4 + ic) * QS_STRIDE + j];
                #pragma unroll
                for (int hc = 0; hc < 4; ++hc)
                    o[ic][hc] += p * vv[hc];
            }
        }
    }

    #pragma unroll
    for (int ic = 0; ic < 4; ++ic) {
        float inv = 1.0f / l[ic];
        int row = b * T + qt * 64 + ti * 4 + ic;
        float4 r = make_float4(o[ic][0] * inv, o[ic][1] * inv,
                               o[ic][2] * inv, o[ic][3] * inv);
        *(float4*)&out[row * H + tj * 4] = r;
    }
}

// ---------------------------------------------------------------------------
extern "C" void kernel_launch(void* const* d_in, const int* in_sizes, int n_in,
                              void* d_out, int out_size)
{
    const float* x  = (const float*)d_in[0];
    const float* Wq = (const float*)d_in[1];
    const float* Wk = (const float*)d_in[2];
    const float* Wv = (const float*)d_in[3];
    float* out = (float*)d_out;

    qkv_proj_kernel<<<BT / 64, 256>>>(x, Wq, Wk, Wv);

    cudaFuncSetAttribute(attn_kernel,
                         cudaFuncAttributeMaxDynamicSharedMemorySize,
                         ATTN_SMEM_BYTES);
    attn_kernel<<<dim3(T / 64, BATCH), 256, ATTN_SMEM_BYTES>>>(out);
}

// round 2
// speedup vs baseline: 2.6046x; 2.6046x over previous
#include <cuda_runtime.h>
#include <cstdint>

#define BATCH 64
#define T 512
#define C 384
#define H 64
#define BT (BATCH*T)

// Projected Q,K,V stored as tf32 bit patterns (uint32). 24 MB total, device globals.
__device__ uint32_t g_Q[BT * H];
__device__ uint32_t g_K[BT * H];
__device__ uint32_t g_V[BT * H];

__device__ __forceinline__ uint32_t f2tf32(float f) {
    uint32_t r;
    asm("cvt.rna.tf32.f32 %0, %1;" : "=r"(r) : "f"(f));
    return r;
}

__device__ __forceinline__ void mma_tf32(float c[4], const uint32_t a[4], const uint32_t b[2]) {
    asm volatile(
        "mma.sync.aligned.m16n8k8.row.col.f32.tf32.tf32.f32 "
        "{%0,%1,%2,%3}, {%4,%5,%6,%7}, {%8,%9}, {%0,%1,%2,%3};\n"
        : "+f"(c[0]), "+f"(c[1]), "+f"(c[2]), "+f"(c[3])
        : "r"(a[0]), "r"(a[1]), "r"(a[2]), "r"(a[3]), "r"(b[0]), "r"(b[1]));
}

// ---------------------------------------------------------------------------
// Kernel 1: QKV projection, TF32 mma.  x[BT,384] @ W[384,64] -> tf32 bits.
// Grid (BT/128, 3).  256 threads = 8 warps as 4(M) x 2(N), warp tile 32x32.
// ---------------------------------------------------------------------------
#define QBM 128
#define QBK 32
#define AS_STR 36   // bank map: 4*g + tg  -> conflict free for A-frag pattern
#define BS_STR 72   // bank map: 8*tg + g  -> conflict free for B-frag pattern

__global__ __launch_bounds__(256) void qkv_proj_kernel(
    const float* __restrict__ x,
    const float* __restrict__ Wq,
    const float* __restrict__ Wk,
    const float* __restrict__ Wv)
{
    __shared__ uint32_t As[QBM][AS_STR];   // [m][k]
    __shared__ uint32_t Bs[QBK][BS_STR];   // [k][n]

    const float* Ws[3] = {Wq, Wk, Wv};
    uint32_t* Outs[3]  = {g_Q, g_K, g_V};
    const int wsel = blockIdx.y;
    const float* W = Ws[wsel];

    const int tid  = threadIdx.x;
    const int lane = tid & 31;
    const int wid  = tid >> 5;
    const int warpM = wid & 3;
    const int warpN = wid >> 2;
    const int g  = lane >> 2;
    const int tg = lane & 3;
    const int row0 = blockIdx.x * QBM;

    float c[2][4][4];
    #pragma unroll
    for (int mf = 0; mf < 2; ++mf)
        #pragma unroll
        for (int nf = 0; nf < 4; ++nf)
            #pragma unroll
            for (int j = 0; j < 4; ++j) c[mf][nf][j] = 0.0f;

    for (int kt = 0; kt < C / QBK; ++kt) {
        // Load X tile 128x32 (1024 float4 slots, 4 per thread)
        #pragma unroll
        for (int i = 0; i < 4; ++i) {
            int s = tid + i * 256;
            int r = s >> 3;
            int c4 = (s & 7) * 4;
            float4 v = *(const float4*)&x[(row0 + r) * C + kt * QBK + c4];
            As[r][c4 + 0] = f2tf32(v.x);
            As[r][c4 + 1] = f2tf32(v.y);
            As[r][c4 + 2] = f2tf32(v.z);
            As[r][c4 + 3] = f2tf32(v.w);
        }
        // Load W tile 32x64 (512 float4 slots, 2 per thread)
        #pragma unroll
        for (int i = 0; i < 2; ++i) {
            int s = tid + i * 256;
            int r = s >> 4;
            int c4 = (s & 15) * 4;
            float4 v = *(const float4*)&W[(kt * QBK + r) * H + c4];
            Bs[r][c4 + 0] = f2tf32(v.x);
            Bs[r][c4 + 1] = f2tf32(v.y);
            Bs[r][c4 + 2] = f2tf32(v.z);
            Bs[r][c4 + 3] = f2tf32(v.w);
        }
        __syncthreads();

        #pragma unroll
        for (int ks = 0; ks < QBK / 8; ++ks) {
            uint32_t a[2][4], b[4][2];
            #pragma unroll
            for (int mf = 0; mf < 2; ++mf) {
                int r = warpM * 32 + mf * 16 + g;
                int k = ks * 8 + tg;
                a[mf][0] = As[r][k];
                a[mf][1] = As[r + 8][k];
                a[mf][2] = As[r][k + 4];
                a[mf][3] = As[r + 8][k + 4];
            }
            #pragma unroll
            for (int nf = 0; nf < 4; ++nf) {
                int k = ks * 8 + tg;
                int n = warpN * 32 + nf * 8 + g;
                b[nf][0] = Bs[k][n];
                b[nf][1] = Bs[k + 4][n];
            }
            #pragma unroll
            for (int mf = 0; mf < 2; ++mf)
                #pragma unroll
                for (int nf = 0; nf < 4; ++nf)
                    mma_tf32(c[mf][nf], a[mf], b[nf]);
        }
        __syncthreads();
    }

    uint32_t* O = Outs[wsel];
    #pragma unroll
    for (int mf = 0; mf < 2; ++mf) {
        int r = row0 + warpM * 32 + mf * 16 + g;
        #pragma unroll
        for (int nf = 0; nf < 4; ++nf) {
            int col = warpN * 32 + nf * 8 + 2 * tg;
            uint2 v0 = make_uint2(f2tf32(c[mf][nf][0]), f2tf32(c[mf][nf][1]));
            uint2 v1 = make_uint2(f2tf32(c[mf][nf][2]), f2tf32(c[mf][nf][3]));
            *(uint2*)&O[r * H + col]        = v0;
            *(uint2*)&O[(r + 8) * H + col]  = v1;
        }
    }
}

// ---------------------------------------------------------------------------
// Kernel 2: causal flash attention with TF32 mma.
// Grid (T/64, BATCH), 128 threads = 4 warps; warp owns 16 q-rows x 64 cols.
// Q frags register-resident. S->softmax in regs (quad shfl), P via smem, PV mma.
// ---------------------------------------------------------------------------
#define QS_STR 68   // A-frag pattern (row=g, col=tg): 4g+tg  -> conflict free
#define KS_STR 68   // QK B-frag (key=g, h=tg):       4g+tg  -> conflict free
#define VS_STR 72   // PV B-frag (key=tg, h=g):       8tg+g  -> conflict free
#define PS_STR 68   // PV A-frag (row=g, key=tg):     4g+tg  -> conflict free
#define ATTN_SMEM_U32 (64 * (QS_STR + KS_STR + VS_STR + PS_STR))
#define ATTN_SMEM_BYTES (ATTN_SMEM_U32 * 4)

__global__ __launch_bounds__(128) void attn_kernel(float* __restrict__ out)
{
    extern __shared__ uint32_t sm[];
    uint32_t* Qs = sm;
    uint32_t* Ks = Qs + 64 * QS_STR;
    uint32_t* Vs = Ks + 64 * KS_STR;
    uint32_t* Ps = Vs + 64 * VS_STR;

    const int tid  = threadIdx.x;
    const int lane = tid & 31;
    const int wid  = tid >> 5;        // 0..3
    const int g    = lane >> 2;
    const int tg   = lane & 3;
    const int qt = blockIdx.x;
    const int b  = blockIdx.y;
    const float scale = 0.125f;       // 1/sqrt(64)

    // Load Q tile (already tf32 bits): 4096 u32 = 1024 uint4, 8 per thread
    const int qoff = (b * T + qt * 64) * H;
    #pragma unroll
    for (int i = 0; i < 8; ++i) {
        int s = tid + i * 128;
        int r = s >> 4;
        int c4 = (s & 15) * 4;
        uint4 v = *(const uint4*)&g_Q[qoff + r * H + c4];
        Qs[r * QS_STR + c4 + 0] = v.x;
        Qs[r * QS_STR + c4 + 1] = v.y;
        Qs[r * QS_STR + c4 + 2] = v.z;
        Qs[r * QS_STR + c4 + 3] = v.w;
    }
    __syncthreads();

    // Q fragments: warp row base = wid*16
    uint32_t qa[8][4];
    const int qrow = wid * 16 + g;
    #pragma unroll
    for (int ks = 0; ks < 8; ++ks) {
        int k = ks * 8 + tg;
        qa[ks][0] = Qs[qrow * QS_STR + k];
        qa[ks][1] = Qs[(qrow + 8) * QS_STR + k];
        qa[ks][2] = Qs[qrow * QS_STR + k + 4];
        qa[ks][3] = Qs[(qrow + 8) * QS_STR + k + 4];
    }

    float m[2] = {-1e30f, -1e30f};
    float l[2] = {0.0f, 0.0f};
    float o[8][4];
    #pragma unroll
    for (int nf = 0; nf < 8; ++nf)
        #pragma unroll
        for (int j = 0; j < 4; ++j) o[nf][j] = 0.0f;

    for (int t = 0; t <= qt; ++t) {
        __syncthreads();   // all PV reads of Ks/Vs/Ps done
        const int koff = (b * T + t * 64) * H;
        #pragma unroll
        for (int i = 0; i < 8; ++i) {
            int s = tid + i * 128;
            int r = s >> 4;
            int c4 = (s & 15) * 4;
            uint4 kv = *(const uint4*)&g_K[koff + r * H + c4];
            Ks[r * KS_STR + c4 + 0] = kv.x;
            Ks[r * KS_STR + c4 + 1] = kv.y;
            Ks[r * KS_STR + c4 + 2] = kv.z;
            Ks[r * KS_STR + c4 + 3] = kv.w;
            uint4 vv = *(const uint4*)&g_V[koff + r * H + c4];
            Vs[r * VS_STR + c4 + 0] = vv.x;
            Vs[r * VS_STR + c4 + 1] = vv.y;
            Vs[r * VS_STR + c4 + 2] = vv.z;
            Vs[r * VS_STR + c4 + 3] = vv.w;
        }
        __syncthreads();

        // --- S = Q K^T : warp computes 16 x 64 ---
        float sf[8][4];
        #pragma unroll
        for (int nf = 0; nf < 8; ++nf)
            #pragma unroll
            for (int j = 0; j < 4; ++j) sf[nf][j] = 0.0f;

        #pragma unroll
        for (int ks = 0; ks < 8; ++ks) {
            int k = ks * 8 + tg;
            #pragma unroll
            for (int nf = 0; nf < 8; ++nf) {
                uint32_t bf[2];
                int key = nf * 8 + g;
                bf[0] = Ks[key * KS_STR + k];
                bf[1] = Ks[key * KS_STR + k + 4];
                mma_tf32(sf[nf], qa[ks], bf);
            }
        }

        // --- online softmax ---
        const bool last = (t == qt);
        float mnew[2] = {m[0], m[1]};
        #pragma unroll
        for (int nf = 0; nf < 8; ++nf) {
            #pragma unroll
            for (int j = 0; j < 4; ++j) {
                int rr = j >> 1;
                float v = sf[nf][j] * scale;
                if (last) {
                    int col = nf * 8 + 2 * tg + (j & 1);
                    int row = wid * 16 + g + rr * 8;
                    if (col > row) v = -1e30f;
                }
                sf[nf][j] = v;
                mnew[rr] = fmaxf(mnew[rr], v);
            }
        }
        #pragma unroll
        for (int rr = 0; rr < 2; ++rr) {
            mnew[rr] = fmaxf(mnew[rr], __shfl_xor_sync(0xffffffffu, mnew[rr], 1));
            mnew[rr] = fmaxf(mnew[rr], __shfl_xor_sync(0xffffffffu, mnew[rr], 2));
        }
        float alpha[2];
        #pragma unroll
        for (int rr = 0; rr < 2; ++rr) {
            alpha[rr] = __expf(m[rr] - mnew[rr]);
            m[rr] = mnew[rr];
        }
        float ls[2] = {0.0f, 0.0f};
        #pragma unroll
        for (int nf = 0; nf < 8; ++nf) {
            #pragma unroll
            for (int j = 0; j < 4; ++j) {
                int rr = j >> 1;
                float p = __expf(sf[nf][j] - m[rr]);
                sf[nf][j] = p;
                ls[rr] += p;
            }
        }
        #pragma unroll
        for (int rr = 0; rr < 2; ++rr) {
            ls[rr] += __shfl_xor_sync(0xffffffffu, ls[rr], 1);
            ls[rr] += __shfl_xor_sync(0xffffffffu, ls[rr], 2);
            l[rr] = l[rr] * alpha[rr] + ls[rr];
        }
        #pragma unroll
        for (int nf = 0; nf < 8; ++nf) {
            o[nf][0] *= alpha[0];
            o[nf][1] *= alpha[0];
            o[nf][2] *= alpha[1];
            o[nf][3] *= alpha[1];
        }

        // store P (tf32) to smem for PV A-fragments
        const int prow = wid * 16 + g;
        #pragma unroll
        for (int nf = 0; nf < 8; ++nf) {
            int col = nf * 8 + 2 * tg;
            *(uint2*)&Ps[prow * PS_STR + col] =
                make_uint2(f2tf32(sf[nf][0]), f2tf32(sf[nf][1]));
            *(uint2*)&Ps[(prow + 8) * PS_STR + col] =
                make_uint2(f2tf32(sf[nf][2]), f2tf32(sf[nf][3]));
        }
        __syncthreads();

        // --- O += P V : warp computes 16 x 64 ---
        #pragma unroll
        for (int ks = 0; ks < 8; ++ks) {
            uint32_t pa[4];
            int k = ks * 8 + tg;
            pa[0] = Ps[prow * PS_STR + k];
            pa[1] = Ps[(prow + 8) * PS_STR + k];
            pa[2] = Ps[prow * PS_STR + k + 4];
            pa[3] = Ps[(prow + 8) * PS_STR + k + 4];
            #pragma unroll
            for (int nf = 0; nf < 8; ++nf) {
                uint32_t bf[2];
                int hh = nf * 8 + g;
                bf[0] = Vs[(ks * 8 + tg) * VS_STR + hh];
                bf[1] = Vs[(ks * 8 + tg + 4) * VS_STR + hh];
                mma_tf32(o[nf], pa, bf);
            }
        }
    }

    // epilogue
    const float inv0 = 1.0f / l[0];
    const float inv1 = 1.0f / l[1];
    const int grow = b * T + qt * 64 + wid * 16 + g;
    #pragma unroll
    for (int nf = 0; nf < 8; ++nf) {
        int col = nf * 8 + 2 * tg;
        *(float2*)&out[grow * H + col] =
            make_float2(o[nf][0] * inv0, o[nf][1] * inv0);
        *(float2*)&out[(grow + 8) * H + col] =
            make_float2(o[nf][2] * inv1, o[nf][3] * inv1);
    }
}

// ---------------------------------------------------------------------------
extern "C" void kernel_launch(void* const* d_in, const int* in_sizes, int n_in,
                              void* d_out, int out_size)
{
    const float* x  = (const float*)d_in[0];
    const float* Wq = (const float*)d_in[1];
    const float* Wk = (const float*)d_in[2];
    const float* Wv = (const float*)d_in[3];
    float* out = (float*)d_out;

    qkv_proj_kernel<<<dim3(BT / QBM, 3), 256>>>(x, Wq, Wk, Wv);

    cudaFuncSetAttribute(attn_kernel,
                         cudaFuncAttributeMaxDynamicSharedMemorySize,
                         ATTN_SMEM_BYTES);
    attn_kernel<<<dim3(T / 64, BATCH), 128, ATTN_SMEM_BYTES>>>(out);
}